// round 1
// baseline (speedup 1.0000x reference)
#include <cuda_runtime.h>
#include <math.h>

// Problem constants (fixed shapes)
#define B 128
#define L 512
#define H 512
#define V 50000

// ---------------------------------------------------------------------------
// Scratch state (static device globals; no runtime allocation)
// ---------------------------------------------------------------------------
__device__ float g_h[2][B * H];   // double-buffered hidden state
__device__ float g_c[B * H];      // cell state (block-exclusive per step)

// ---------------------------------------------------------------------------
// Init: zero h[0] and c
// ---------------------------------------------------------------------------
__global__ void k_init() {
    int i = blockIdx.x * blockDim.x + threadIdx.x;
    if (i < B * H) {
        g_h[0][i] = 0.f;
        g_c[i]    = 0.f;
    }
}

// ---------------------------------------------------------------------------
// One LSTM timestep, fused:
//   gates[b, r] = sum_k  [x_t(b) ; h_prev(b)](k) * [W_ih ; W_hh](r, k)
//                 + b_ih[r] + b_hh[r]
//   then i,f,g,o activations, c/h update with length masking.
//
// Grid: (16 col-groups of 32 h-cols, 8 batch-groups of 16 batches), 256 thr.
// Block computes tile: 16 batches x 128 gate-rows (i/f/g/o x 32 cols), K=1024.
// h is double-buffered across steps to avoid cross-block RAW races.
// ---------------------------------------------------------------------------
__global__ void __launch_bounds__(256, 1)
k_step(const int* __restrict__ tokens, const int* __restrict__ lengths,
       const float* __restrict__ emb,  const float* __restrict__ Wih,
       const float* __restrict__ Whh,  const float* __restrict__ bih,
       const float* __restrict__ bhh,  int t, int par)
{
    __shared__ float As[16][33];    // [batch][k-slice]
    __shared__ float Ws[128][33];   // [local gate row][k-slice]
    __shared__ float Gs[16][128];   // gate accumulators for pointwise
    __shared__ int   toks[16];

    const int tid       = threadIdx.x;
    const int colBase   = blockIdx.x * 32;   // h-column base (0..511)
    const int batchBase = blockIdx.y * 16;   // batch base

    if (tid < 16) toks[tid] = tokens[(batchBase + tid) * L + t];
    __syncthreads();

    const int bt = tid >> 5;   // warp id 0..7 -> owns batches {2bt, 2bt+1}
    const int rt = tid & 31;   // lane        -> owns rows {rt, rt+32, rt+64, rt+96}

    float acc[2][4] = {{0.f, 0.f, 0.f, 0.f}, {0.f, 0.f, 0.f, 0.f}};
    const float* __restrict__ hprev = g_h[par];

    // K = 1024 in 32 slices of 32. Slices 0..15 come from the embedding /
    // W_ih half; slices 16..31 from h / W_hh.
    for (int kc = 0; kc < 32; kc++) {
        const int kbase = kc * 32;

        // --- stage A tile: 16 batches x 32 k  (2 elems / thread) ---
        {
            int idx = tid;
            #pragma unroll
            for (int rep = 0; rep < 2; rep++, idx += 256) {
                int b = idx >> 5, k = idx & 31;
                int kg = kbase + k;
                float v;
                if (kg < 512) v = emb[toks[b] * H + kg];
                else          v = hprev[(batchBase + b) * H + (kg - 512)];
                As[b][k] = v;
            }
        }
        // --- stage W tile: 128 rows x 32 k  (16 elems / thread) ---
        {
            const float* __restrict__ src = (kbase < 512) ? Wih : Whh;
            const int koff = (kbase < 512) ? kbase : (kbase - 512);
            #pragma unroll
            for (int rep = 0; rep < 16; rep++) {
                int idx = tid + 256 * rep;
                int r = idx >> 5, k = idx & 31;
                // local row r: gate = r>>5 (i,f,g,o), col = r&31
                int grow = ((r >> 5) << 9) + colBase + (r & 31);
                Ws[r][k] = src[grow * H + koff + k];
            }
        }
        __syncthreads();

        #pragma unroll
        for (int k = 0; k < 32; k++) {
            float a0 = As[2 * bt][k];
            float a1 = As[2 * bt + 1][k];
            #pragma unroll
            for (int j = 0; j < 4; j++) {
                float w = Ws[rt + 32 * j][k];
                acc[0][j] = fmaf(a0, w, acc[0][j]);
                acc[1][j] = fmaf(a1, w, acc[1][j]);
            }
        }
        __syncthreads();
    }

    // Park gate sums in smem for the pointwise phase
    #pragma unroll
    for (int j = 0; j < 4; j++) {
        Gs[2 * bt][rt + 32 * j]     = acc[0][j];
        Gs[2 * bt + 1][rt + 32 * j] = acc[1][j];
    }
    __syncthreads();

    // --- pointwise gate update: 512 (b, col) pairs, 2 per thread ---
    #pragma unroll
    for (int rep = 0; rep < 2; rep++) {
        int p = tid + 256 * rep;
        int b = p >> 5, c = p & 31;
        int gb = batchBase + b;
        int gc = colBase + c;
        int r0 = gc, r1 = 512 + gc, r2 = 1024 + gc, r3 = 1536 + gc;

        float xi = Gs[b][c]      + bih[r0] + bhh[r0];
        float xf = Gs[b][32 + c] + bih[r1] + bhh[r1];
        float xg = Gs[b][64 + c] + bih[r2] + bhh[r2];
        float xo = Gs[b][96 + c] + bih[r3] + bhh[r3];

        float ig = 1.f / (1.f + expf(-xi));
        float fg = 1.f / (1.f + expf(-xf));
        float gg = tanhf(xg);
        float og = 1.f / (1.f + expf(-xo));

        int   hi   = gb * H + gc;
        float cold = g_c[hi];
        float cn   = fg * cold + ig * gg;
        float hn   = og * tanhf(cn);

        bool valid = (t < lengths[gb]);
        float hold = hprev[hi];
        g_h[par ^ 1][hi] = valid ? hn : hold;  // always write next buffer
        if (valid) g_c[hi] = cn;               // c frozen when invalid
    }
}

// ---------------------------------------------------------------------------
// FC: out[b, v] = h_final[b, :] . W_fc[v, :] + b_fc[v]
// Tile 128(batch) x 128(vocab), K=512, BK=16, 256 threads, 8x8 per thread.
// ---------------------------------------------------------------------------
__global__ void __launch_bounds__(256, 1)
k_fc(const float* __restrict__ Wfc, const float* __restrict__ bfc,
     float* __restrict__ out)
{
    __shared__ float As[16][128];
    __shared__ float Bs[16][128];

    const int vBase = blockIdx.x * 128;
    const int tid   = threadIdx.x;
    const int ty    = tid >> 4;   // 0..15 -> batch rows ty*8..
    const int tx    = tid & 15;   // 0..15 -> vocab cols tx*8..

    const float* __restrict__ hptr = g_h[0];  // final h after 512 steps

    float acc[8][8];
    #pragma unroll
    for (int i = 0; i < 8; i++)
        #pragma unroll
        for (int j = 0; j < 8; j++) acc[i][j] = 0.f;

    for (int k0 = 0; k0 < H; k0 += 16) {
        #pragma unroll
        for (int r = 0; r < 8; r++) {
            int idx = tid + 256 * r;
            int m = idx >> 4, k = idx & 15;
            As[k][m] = hptr[m * H + k0 + k];
        }
        #pragma unroll
        for (int r = 0; r < 8; r++) {
            int idx = tid + 256 * r;
            int v = idx >> 4, k = idx & 15;
            int gv = vBase + v;
            Bs[k][v] = (gv < V) ? Wfc[gv * H + k0 + k] : 0.f;
        }
        __syncthreads();

        #pragma unroll
        for (int k = 0; k < 16; k++) {
            float a[8], b[8];
            *(float4*)&a[0] = *(const float4*)&As[k][ty * 8];
            *(float4*)&a[4] = *(const float4*)&As[k][ty * 8 + 4];
            *(float4*)&b[0] = *(const float4*)&Bs[k][tx * 8];
            *(float4*)&b[4] = *(const float4*)&Bs[k][tx * 8 + 4];
            #pragma unroll
            for (int i = 0; i < 8; i++)
                #pragma unroll
                for (int j = 0; j < 8; j++)
                    acc[i][j] = fmaf(a[i], b[j], acc[i][j]);
        }
        __syncthreads();
    }

    #pragma unroll
    for (int i = 0; i < 8; i++) {
        int m = ty * 8 + i;
        #pragma unroll
        for (int j = 0; j < 8; j++) {
            int gv = vBase + tx * 8 + j;
            if (gv < V) out[m * V + gv] = acc[i][j] + bfc[gv];
        }
    }
}

// ---------------------------------------------------------------------------
// Launch
// ---------------------------------------------------------------------------
extern "C" void kernel_launch(void* const* d_in, const int* in_sizes, int n_in,
                              void* d_out, int out_size)
{
    const int*   tokens  = (const int*)  d_in[0];
    const int*   lengths = (const int*)  d_in[1];
    const float* emb     = (const float*)d_in[2];
    const float* Wih     = (const float*)d_in[3];
    const float* Whh     = (const float*)d_in[4];
    const float* bih     = (const float*)d_in[5];
    const float* bhh     = (const float*)d_in[6];
    const float* Wfc     = (const float*)d_in[7];
    const float* bfc     = (const float*)d_in[8];
    float* out = (float*)d_out;

    k_init<<<(B * H + 255) / 256, 256>>>();

    dim3 sgrid(16, 8);  // 16 col-groups x 8 batch-groups
    for (int t = 0; t < L; t++) {
        k_step<<<sgrid, 256>>>(tokens, lengths, emb, Wih, Whh, bih, bhh,
                               t, t & 1);
    }

    k_fc<<<(V + 127) / 128, 256>>>(Wfc, bfc, out);
}

// round 2
// speedup vs baseline: 1.2501x; 1.2501x over previous
#include <cuda_runtime.h>
#include <math.h>

// Problem constants
#define B 128
#define L 512
#define H 512
#define V 50000

#define NBLK 128   // persistent blocks (one per SM, all co-resident)
#define NTHR 256

#define BPAD 136   // As row pad (conflict-free STS, 16B-aligned LDS.128)
#define GPAD 132   // Gs row pad

// ---------------------------------------------------------------------------
// Device globals (no runtime allocation allowed)
// ---------------------------------------------------------------------------
__device__ float    g_h[2][B * H];   // double-buffered hidden state
__device__ int      g_tokT[L * B];   // transposed tokens [t][b]
__device__ unsigned g_arrive;        // grid barrier counter (monotonic)

// ---------------------------------------------------------------------------
// Packed f32x2 helpers (Blackwell; ptxas never auto-fuses — PTX required)
// ---------------------------------------------------------------------------
__device__ __forceinline__ unsigned long long packf2(float x, float y) {
    unsigned long long r;
    asm("mov.b64 %0, {%1, %2};" : "=l"(r) : "f"(x), "f"(y));
    return r;
}
__device__ __forceinline__ float2 unpackf2(unsigned long long v) {
    float2 r;
    asm("mov.b64 {%0, %1}, %2;" : "=f"(r.x), "=f"(r.y) : "l"(v));
    return r;
}
__device__ __forceinline__ void fma2(unsigned long long& d,
                                     unsigned long long a,
                                     unsigned long long b) {
    asm("fma.rn.f32x2 %0, %1, %2, %0;" : "+l"(d) : "l"(a), "l"(b));
}

// ---------------------------------------------------------------------------
// Init: zero h buffers, transpose tokens, reset barrier counter
// ---------------------------------------------------------------------------
__global__ void k_init(const int* __restrict__ tokens) {
    int i = blockIdx.x * blockDim.x + threadIdx.x;
    if (i < B * H) { g_h[0][i] = 0.f; g_h[1][i] = 0.f; }
    if (i < L * B) {
        int t = i >> 7, b = i & 127;           // coalesced write g_tokT[i]
        g_tokT[i] = tokens[b * L + t];
    }
    if (i == 0) g_arrive = 0u;
}

// ---------------------------------------------------------------------------
// Persistent LSTM recurrence kernel.
// Block bx owns h-columns [4bx, 4bx+4) -> 16 gate rows {g*512 + 4bx + cc}.
// Weights for those 16 rows (K=1024 concat [W_ih;W_hh]) stay in smem.
// c and h live in registers per thread; h broadcast via double-buffered global.
// One software grid barrier per step.
// ---------------------------------------------------------------------------
extern __shared__ float smem[];

__global__ void __launch_bounds__(NTHR, 1)
k_lstm(const int*   __restrict__ lengths, const float* __restrict__ emb,
       const float* __restrict__ Wih,     const float* __restrict__ Whh,
       const float* __restrict__ bih,     const float* __restrict__ bhh)
{
    float* Ws = smem;                       // [1024][16]  k-major weights
    float* As = Ws + 1024 * 16;             // [2][32][BPAD] staged A (k-major)
    float* Gs = As + 2 * 32 * BPAD;         // [16][GPAD]  gate sums
    float* bs = Gs + 16 * GPAD;             // [16] combined biases

    const int tid  = threadIdx.x;
    const int bx   = blockIdx.x;            // column group
    const int warp = tid >> 5;
    const int lane = tid & 31;
    const int r2   = lane & 7;              // row pair: rows {2r2, 2r2+1}
    const int b4   = lane >> 3;             // batch quad within warp
    const int qb   = warp * 16 + b4 * 4;    // batch quad base (0..124)
    const int sb   = tid >> 5;              // staging batch base lane group

    // ---- load persistent weight tile: 16 rows x 1024 k ----
    for (int idx = tid; idx < 16 * 1024; idx += NTHR) {
        int lr = idx >> 10;                 // local row 0..15
        int kk = idx & 1023;
        int g = lr >> 2, cc = lr & 3;
        int grow = g * 512 + bx * 4 + cc;
        float w = (kk < 512) ? Wih[grow * 512 + kk]
                             : Whh[grow * 512 + (kk - 512)];
        Ws[kk * 16 + lr] = w;
    }
    if (tid < 16) {
        int g = tid >> 2, cc = tid & 3;
        int grow = g * 512 + bx * 4 + cc;
        bs[tid] = bih[grow] + bhh[grow];
    }

    // ---- per-thread pointwise state: 2 (batch, col) pairs ----
    const int pb0 = tid >> 2;               // batch 0..63
    const int pb1 = pb0 + 64;               // batch 64..127
    const int pc  = tid & 3;                // local col
    const int hcol = bx * 4 + pc;
    float c_reg[2] = {0.f, 0.f};
    float h_reg[2] = {0.f, 0.f};
    const int len0 = lengths[pb0];
    const int len1 = lengths[pb1];

    __syncthreads();

    for (int t = 0; t < L; t++) {
        const int rb = t & 1, wb = rb ^ 1;
        const float* __restrict__ hprev = g_h[rb];

        // tokens for my 16 staged batches (uniform per warp)
        int mytok[16];
        #pragma unroll
        for (int rep = 0; rep < 16; rep++)
            mytok[rep] = g_tokT[t * 128 + sb + 8 * rep];

        // ---- stage chunk 0 (k = 0..31, embedding half) ----
        float v[16];
        {
            int k = lane;
            #pragma unroll
            for (int rep = 0; rep < 16; rep++)
                v[rep] = emb[mytok[rep] * 512 + k];
            float* dst = As + k * BPAD;     // buffer 0
            #pragma unroll
            for (int rep = 0; rep < 16; rep++)
                dst[sb + 8 * rep] = v[rep];
        }
        __syncthreads();

        unsigned long long acc00 = 0, acc01 = 0, acc10 = 0, acc11 = 0;

        for (int kc = 0; kc < 32; kc++) {
            // prefetch chunk kc+1 into registers (overlaps with compute)
            if (kc + 1 < 32) {
                int kg = (kc + 1) * 32 + lane;
                if (kg < 512) {
                    #pragma unroll
                    for (int rep = 0; rep < 16; rep++)
                        v[rep] = emb[mytok[rep] * 512 + kg];
                } else {
                    int ko = kg - 512;
                    #pragma unroll
                    for (int rep = 0; rep < 16; rep++)
                        v[rep] = __ldcg(hprev + (sb + 8 * rep) * 512 + ko);
                }
            }

            // compute on buffer kc&1 : 32 k-steps
            const float* Asb = As + (kc & 1) * 32 * BPAD;
            const float* Wsk = Ws + kc * 32 * 16;
            #pragma unroll 8
            for (int k = 0; k < 32; k++) {
                ulonglong2 a = *(const ulonglong2*)(Asb + k * BPAD + qb);
                float2 wv    = *(const float2*)(Wsk + k * 16 + 2 * r2);
                unsigned long long w0 = packf2(wv.x, wv.x);
                unsigned long long w1 = packf2(wv.y, wv.y);
                fma2(acc00, a.x, w0);  fma2(acc01, a.y, w0);
                fma2(acc10, a.x, w1);  fma2(acc11, a.y, w1);
            }

            // commit prefetched chunk into the other buffer
            if (kc + 1 < 32) {
                float* dst = As + ((kc + 1) & 1) * 32 * BPAD + lane * BPAD;
                #pragma unroll
                for (int rep = 0; rep < 16; rep++)
                    dst[sb + 8 * rep] = v[rep];
            }
            __syncthreads();
        }

        // ---- park gate sums in smem ----
        {
            float* g0 = Gs + (2 * r2) * GPAD + qb;
            float* g1 = Gs + (2 * r2 + 1) * GPAD + qb;
            *(float2*)(g0)     = unpackf2(acc00);
            *(float2*)(g0 + 2) = unpackf2(acc01);
            *(float2*)(g1)     = unpackf2(acc10);
            *(float2*)(g1 + 2) = unpackf2(acc11);
        }
        __syncthreads();

        // ---- pointwise gates + state update (2 pairs per thread) ----
        #pragma unroll
        for (int pp = 0; pp < 2; pp++) {
            int b   = pp ? pb1 : pb0;
            int len = pp ? len1 : len0;
            float xi = Gs[(0 + pc) * GPAD + b]  + bs[0 + pc];
            float xf = Gs[(4 + pc) * GPAD + b]  + bs[4 + pc];
            float xg = Gs[(8 + pc) * GPAD + b]  + bs[8 + pc];
            float xo = Gs[(12 + pc) * GPAD + b] + bs[12 + pc];

            float ig = 1.f / (1.f + expf(-xi));
            float fg = 1.f / (1.f + expf(-xf));
            float gg = tanhf(xg);
            float og = 1.f / (1.f + expf(-xo));

            if (t < len) {
                c_reg[pp] = fg * c_reg[pp] + ig * gg;
                h_reg[pp] = og * tanhf(c_reg[pp]);
            }
            g_h[wb][b * H + hcol] = h_reg[pp];
        }

        // ---- software grid barrier (release: fence by every thread) ----
        __threadfence();
        __syncthreads();
        if (tid == 0) {
            unsigned target = (unsigned)NBLK * (unsigned)(t + 1);
            atomicAdd(&g_arrive, 1u);
            while (*(volatile unsigned*)&g_arrive < target) { }
        }
        __syncthreads();
    }
}

// ---------------------------------------------------------------------------
// FC: out[b, v] = h_final[b, :] . W_fc[v, :] + b_fc[v]
// (final h lands in g_h[0] since L is even)
// ---------------------------------------------------------------------------
__global__ void __launch_bounds__(256, 1)
k_fc(const float* __restrict__ Wfc, const float* __restrict__ bfc,
     float* __restrict__ out)
{
    __shared__ float As_[16][128];
    __shared__ float Bs_[16][128];

    const int vBase = blockIdx.x * 128;
    const int tid   = threadIdx.x;
    const int ty    = tid >> 4;
    const int tx    = tid & 15;

    const float* __restrict__ hptr = g_h[0];

    float acc[8][8];
    #pragma unroll
    for (int i = 0; i < 8; i++)
        #pragma unroll
        for (int j = 0; j < 8; j++) acc[i][j] = 0.f;

    for (int k0 = 0; k0 < H; k0 += 16) {
        #pragma unroll
        for (int r = 0; r < 8; r++) {
            int idx = tid + 256 * r;
            int m = idx >> 4, k = idx & 15;
            As_[k][m] = hptr[m * H + k0 + k];
        }
        #pragma unroll
        for (int r = 0; r < 8; r++) {
            int idx = tid + 256 * r;
            int vv = idx >> 4, k = idx & 15;
            int gv = vBase + vv;
            Bs_[k][vv] = (gv < V) ? Wfc[gv * H + k0 + k] : 0.f;
        }
        __syncthreads();

        #pragma unroll
        for (int k = 0; k < 16; k++) {
            float a[8], b[8];
            *(float4*)&a[0] = *(const float4*)&As_[k][ty * 8];
            *(float4*)&a[4] = *(const float4*)&As_[k][ty * 8 + 4];
            *(float4*)&b[0] = *(const float4*)&Bs_[k][tx * 8];
            *(float4*)&b[4] = *(const float4*)&Bs_[k][tx * 8 + 4];
            #pragma unroll
            for (int i = 0; i < 8; i++)
                #pragma unroll
                for (int j = 0; j < 8; j++)
                    acc[i][j] = fmaf(a[i], b[j], acc[i][j]);
        }
        __syncthreads();
    }

    #pragma unroll
    for (int i = 0; i < 8; i++) {
        int m = ty * 8 + i;
        #pragma unroll
        for (int j = 0; j < 8; j++) {
            int gv = vBase + tx * 8 + j;
            if (gv < V) out[m * V + gv] = acc[i][j] + bfc[gv];
        }
    }
}

// ---------------------------------------------------------------------------
// Launch
// ---------------------------------------------------------------------------
extern "C" void kernel_launch(void* const* d_in, const int* in_sizes, int n_in,
                              void* d_out, int out_size)
{
    const int*   tokens  = (const int*)  d_in[0];
    const int*   lengths = (const int*)  d_in[1];
    const float* emb     = (const float*)d_in[2];
    const float* Wih     = (const float*)d_in[3];
    const float* Whh     = (const float*)d_in[4];
    const float* bih     = (const float*)d_in[5];
    const float* bhh     = (const float*)d_in[6];
    const float* Wfc     = (const float*)d_in[7];
    const float* bfc     = (const float*)d_in[8];
    float* out = (float*)d_out;

    const int smemBytes = (16 * 1024 + 2 * 32 * BPAD + 16 * GPAD + 16) * 4;
    static bool attrSet = false;
    if (!attrSet) {
        cudaFuncSetAttribute(k_lstm, cudaFuncAttributeMaxDynamicSharedMemorySize,
                             smemBytes);
        attrSet = true;
    }

    k_init<<<(B * H + 255) / 256, 256>>>(tokens);
    k_lstm<<<NBLK, NTHR, smemBytes>>>(lengths, emb, Wih, Whh, bih, bhh);
    k_fc<<<(V + 127) / 128, 256>>>(Wfc, bfc, out);
}

// round 3
// speedup vs baseline: 1.2525x; 1.0019x over previous
#include <cuda_runtime.h>
#include <math.h>

// Problem constants
#define B 128
#define L 512
#define H 512
#define V 50000

#define NBLK 128   // persistent blocks (one per SM, all co-resident)
#define NTHR 256

#define BPAD 136   // As row pad (conflict-free STS, 16B-aligned LDS.128)
#define GPAD 132   // Gs row pad

// ---------------------------------------------------------------------------
// Device globals (no runtime allocation allowed)
// ---------------------------------------------------------------------------
__device__ float    g_h[2][B * H];   // double-buffered hidden state
__device__ int      g_tokT[L * B];   // transposed tokens [t][b]
__device__ unsigned g_arrive;        // grid barrier counter (monotonic)

// ---------------------------------------------------------------------------
// Packed f32x2 helpers (Blackwell; ptxas never auto-fuses — PTX required)
// ---------------------------------------------------------------------------
__device__ __forceinline__ unsigned long long packf2(float x, float y) {
    unsigned long long r;
    asm("mov.b64 %0, {%1, %2};" : "=l"(r) : "f"(x), "f"(y));
    return r;
}
__device__ __forceinline__ float2 unpackf2(unsigned long long v) {
    float2 r;
    asm("mov.b64 {%0, %1}, %2;" : "=f"(r.x), "=f"(r.y) : "l"(v));
    return r;
}
__device__ __forceinline__ void fma2(unsigned long long& d,
                                     unsigned long long a,
                                     unsigned long long b) {
    asm("fma.rn.f32x2 %0, %1, %2, %0;" : "+l"(d) : "l"(a), "l"(b));
}

// ---------------------------------------------------------------------------
// Init: zero h buffers, transpose tokens, reset barrier counter
// ---------------------------------------------------------------------------
__global__ void k_init(const int* __restrict__ tokens) {
    int i = blockIdx.x * blockDim.x + threadIdx.x;
    if (i < B * H) { g_h[0][i] = 0.f; g_h[1][i] = 0.f; }
    if (i < L * B) {
        int t = i >> 7, b = i & 127;           // coalesced write g_tokT[i]
        g_tokT[i] = tokens[b * L + t];
    }
    if (i == 0) g_arrive = 0u;
}

// ---------------------------------------------------------------------------
// Persistent LSTM recurrence kernel.
// Block bx owns h-columns [4bx, 4bx+4) -> 16 gate rows {g*512 + 4bx + cc}.
// Weights for those 16 rows (K=1024 concat [W_ih;W_hh]) stay in smem.
// c and h live in registers per thread; h broadcast via double-buffered global.
// One software grid barrier per step.
// ---------------------------------------------------------------------------
extern __shared__ float smem[];

__global__ void __launch_bounds__(NTHR, 1)
k_lstm(const int*   __restrict__ lengths, const float* __restrict__ emb,
       const float* __restrict__ Wih,     const float* __restrict__ Whh,
       const float* __restrict__ bih,     const float* __restrict__ bhh)
{
    float* Ws = smem;                       // [1024][16]  k-major weights
    float* As = Ws + 1024 * 16;             // [2][32][BPAD] staged A (k-major)
    float* Gs = As + 2 * 32 * BPAD;         // [16][GPAD]  gate sums
    float* bs = Gs + 16 * GPAD;             // [16] combined biases

    const int tid  = threadIdx.x;
    const int bx   = blockIdx.x;            // column group
    const int warp = tid >> 5;
    const int lane = tid & 31;
    const int r2   = lane & 7;              // row pair: rows {2r2, 2r2+1}
    const int b4   = lane >> 3;             // batch quad within warp
    const int qb   = warp * 16 + b4 * 4;    // batch quad base (0..124)
    const int sb   = tid >> 5;              // staging batch base lane group

    // ---- load persistent weight tile: 16 rows x 1024 k ----
    for (int idx = tid; idx < 16 * 1024; idx += NTHR) {
        int lr = idx >> 10;                 // local row 0..15
        int kk = idx & 1023;
        int g = lr >> 2, cc = lr & 3;
        int grow = g * 512 + bx * 4 + cc;
        float w = (kk < 512) ? Wih[grow * 512 + kk]
                             : Whh[grow * 512 + (kk - 512)];
        Ws[kk * 16 + lr] = w;
    }
    if (tid < 16) {
        int g = tid >> 2, cc = tid & 3;
        int grow = g * 512 + bx * 4 + cc;
        bs[tid] = bih[grow] + bhh[grow];
    }

    // ---- per-thread pointwise state: 2 (batch, col) pairs ----
    const int pb0 = tid >> 2;               // batch 0..63
    const int pb1 = pb0 + 64;               // batch 64..127
    const int pc  = tid & 3;                // local col
    const int hcol = bx * 4 + pc;
    float c_reg[2] = {0.f, 0.f};
    float h_reg[2] = {0.f, 0.f};
    const int len0 = lengths[pb0];
    const int len1 = lengths[pb1];

    __syncthreads();

    for (int t = 0; t < L; t++) {
        const int rb = t & 1, wb = rb ^ 1;
        const float* __restrict__ hprev = g_h[rb];

        // tokens for my 16 staged batches (uniform per warp)
        int mytok[16];
        #pragma unroll
        for (int rep = 0; rep < 16; rep++)
            mytok[rep] = g_tokT[t * 128 + sb + 8 * rep];

        // ---- stage chunk 0 (k = 0..31, embedding half) ----
        float v[16];
        {
            int k = lane;
            #pragma unroll
            for (int rep = 0; rep < 16; rep++)
                v[rep] = emb[mytok[rep] * 512 + k];
            float* dst = As + k * BPAD;     // buffer 0
            #pragma unroll
            for (int rep = 0; rep < 16; rep++)
                dst[sb + 8 * rep] = v[rep];
        }
        __syncthreads();

        unsigned long long acc00 = 0, acc01 = 0, acc10 = 0, acc11 = 0;

        for (int kc = 0; kc < 32; kc++) {
            // prefetch chunk kc+1 into registers (overlaps with compute)
            if (kc + 1 < 32) {
                int kg = (kc + 1) * 32 + lane;
                if (kg < 512) {
                    #pragma unroll
                    for (int rep = 0; rep < 16; rep++)
                        v[rep] = emb[mytok[rep] * 512 + kg];
                } else {
                    int ko = kg - 512;
                    #pragma unroll
                    for (int rep = 0; rep < 16; rep++)
                        v[rep] = __ldcg(hprev + (sb + 8 * rep) * 512 + ko);
                }
            }

            // compute on buffer kc&1 : 32 k-steps
            const float* Asb = As + (kc & 1) * 32 * BPAD;
            const float* Wsk = Ws + kc * 32 * 16;
            #pragma unroll 8
            for (int k = 0; k < 32; k++) {
                ulonglong2 a = *(const ulonglong2*)(Asb + k * BPAD + qb);
                float2 wv    = *(const float2*)(Wsk + k * 16 + 2 * r2);
                unsigned long long w0 = packf2(wv.x, wv.x);
                unsigned long long w1 = packf2(wv.y, wv.y);
                fma2(acc00, a.x, w0);  fma2(acc01, a.y, w0);
                fma2(acc10, a.x, w1);  fma2(acc11, a.y, w1);
            }

            // commit prefetched chunk into the other buffer
            if (kc + 1 < 32) {
                float* dst = As + ((kc + 1) & 1) * 32 * BPAD + lane * BPAD;
                #pragma unroll
                for (int rep = 0; rep < 16; rep++)
                    dst[sb + 8 * rep] = v[rep];
            }
            __syncthreads();
        }

        // ---- park gate sums in smem ----
        {
            float* g0 = Gs + (2 * r2) * GPAD + qb;
            float* g1 = Gs + (2 * r2 + 1) * GPAD + qb;
            *(float2*)(g0)     = unpackf2(acc00);
            *(float2*)(g0 + 2) = unpackf2(acc01);
            *(float2*)(g1)     = unpackf2(acc10);
            *(float2*)(g1 + 2) = unpackf2(acc11);
        }
        __syncthreads();

        // ---- pointwise gates + state update (2 pairs per thread) ----
        #pragma unroll
        for (int pp = 0; pp < 2; pp++) {
            int b   = pp ? pb1 : pb0;
            int len = pp ? len1 : len0;
            float xi = Gs[(0 + pc) * GPAD + b]  + bs[0 + pc];
            float xf = Gs[(4 + pc) * GPAD + b]  + bs[4 + pc];
            float xg = Gs[(8 + pc) * GPAD + b]  + bs[8 + pc];
            float xo = Gs[(12 + pc) * GPAD + b] + bs[12 + pc];

            float ig = 1.f / (1.f + expf(-xi));
            float fg = 1.f / (1.f + expf(-xf));
            float gg = tanhf(xg);
            float og = 1.f / (1.f + expf(-xo));

            if (t < len) {
                c_reg[pp] = fg * c_reg[pp] + ig * gg;
                h_reg[pp] = og * tanhf(c_reg[pp]);
            }
            g_h[wb][b * H + hcol] = h_reg[pp];
        }

        // ---- software grid barrier (release: fence by every thread) ----
        __threadfence();
        __syncthreads();
        if (tid == 0) {
            unsigned target = (unsigned)NBLK * (unsigned)(t + 1);
            atomicAdd(&g_arrive, 1u);
            while (*(volatile unsigned*)&g_arrive < target) { }
        }
        __syncthreads();
    }
}

// ---------------------------------------------------------------------------
// FC: out[b, v] = h_final[b, :] . W_fc[v, :] + b_fc[v]
// (final h lands in g_h[0] since L is even)
// ---------------------------------------------------------------------------
__global__ void __launch_bounds__(256, 1)
k_fc(const float* __restrict__ Wfc, const float* __restrict__ bfc,
     float* __restrict__ out)
{
    __shared__ float As_[16][128];
    __shared__ float Bs_[16][128];

    const int vBase = blockIdx.x * 128;
    const int tid   = threadIdx.x;
    const int ty    = tid >> 4;
    const int tx    = tid & 15;

    const float* __restrict__ hptr = g_h[0];

    float acc[8][8];
    #pragma unroll
    for (int i = 0; i < 8; i++)
        #pragma unroll
        for (int j = 0; j < 8; j++) acc[i][j] = 0.f;

    for (int k0 = 0; k0 < H; k0 += 16) {
        #pragma unroll
        for (int r = 0; r < 8; r++) {
            int idx = tid + 256 * r;
            int m = idx >> 4, k = idx & 15;
            As_[k][m] = hptr[m * H + k0 + k];
        }
        #pragma unroll
        for (int r = 0; r < 8; r++) {
            int idx = tid + 256 * r;
            int vv = idx >> 4, k = idx & 15;
            int gv = vBase + vv;
            Bs_[k][vv] = (gv < V) ? Wfc[gv * H + k0 + k] : 0.f;
        }
        __syncthreads();

        #pragma unroll
        for (int k = 0; k < 16; k++) {
            float a[8], b[8];
            *(float4*)&a[0] = *(const float4*)&As_[k][ty * 8];
            *(float4*)&a[4] = *(const float4*)&As_[k][ty * 8 + 4];
            *(float4*)&b[0] = *(const float4*)&Bs_[k][tx * 8];
            *(float4*)&b[4] = *(const float4*)&Bs_[k][tx * 8 + 4];
            #pragma unroll
            for (int i = 0; i < 8; i++)
                #pragma unroll
                for (int j = 0; j < 8; j++)
                    acc[i][j] = fmaf(a[i], b[j], acc[i][j]);
        }
        __syncthreads();
    }

    #pragma unroll
    for (int i = 0; i < 8; i++) {
        int m = ty * 8 + i;
        #pragma unroll
        for (int j = 0; j < 8; j++) {
            int gv = vBase + tx * 8 + j;
            if (gv < V) out[m * V + gv] = acc[i][j] + bfc[gv];
        }
    }
}

// ---------------------------------------------------------------------------
// Launch
// ---------------------------------------------------------------------------
extern "C" void kernel_launch(void* const* d_in, const int* in_sizes, int n_in,
                              void* d_out, int out_size)
{
    const int*   tokens  = (const int*)  d_in[0];
    const int*   lengths = (const int*)  d_in[1];
    const float* emb     = (const float*)d_in[2];
    const float* Wih     = (const float*)d_in[3];
    const float* Whh     = (const float*)d_in[4];
    const float* bih     = (const float*)d_in[5];
    const float* bhh     = (const float*)d_in[6];
    const float* Wfc     = (const float*)d_in[7];
    const float* bfc     = (const float*)d_in[8];
    float* out = (float*)d_out;

    const int smemBytes = (16 * 1024 + 2 * 32 * BPAD + 16 * GPAD + 16) * 4;
    static bool attrSet = false;
    if (!attrSet) {
        cudaFuncSetAttribute(k_lstm, cudaFuncAttributeMaxDynamicSharedMemorySize,
                             smemBytes);
        attrSet = true;
    }

    k_init<<<(B * H + 255) / 256, 256>>>(tokens);
    k_lstm<<<NBLK, NTHR, smemBytes>>>(lengths, emb, Wih, Whh, bih, bhh);
    k_fc<<<(V + 127) / 128, 256>>>(Wfc, bfc, out);
}